// round 1
// baseline (speedup 1.0000x reference)
#include <cuda_runtime.h>
#include <cuda_fp16.h>
#include <stdint.h>
#include <math.h>

// ---------------------------------------------------------------------------
// Problem dims
// ---------------------------------------------------------------------------
#define B_SZ   16384
#define D_IN   1280
#define D_HID  512
#define D_OUT  229
#define K1     (7 * D_IN)    // 8960  (silu + 6 bases per input feature)
#define K2     (7 * D_HID)   // 3584
#define N2PAD  256           // D_OUT padded to BN multiple

// ---------------------------------------------------------------------------
// Scratch (static device globals; no runtime allocation)
// ---------------------------------------------------------------------------
static __device__ __half g_A1[(size_t)B_SZ * K1];    // expanded layer-1 activations (f16)
static __device__ __half g_W1[(size_t)D_HID * K1];   // fused layer-1 weights (f16), [o][k]
static __device__ float  g_h [(size_t)B_SZ * D_HID]; // pre-layernorm hidden (fp32)
static __device__ __half g_A2[(size_t)B_SZ * K2];    // expanded layer-2 activations (f16)
static __device__ __half g_W2[(size_t)N2PAD * K2];   // fused layer-2 weights (f16), zero-padded

// ---------------------------------------------------------------------------
// B-spline bases (matches reference recursion; uniform knots, constant-folded)
// ---------------------------------------------------------------------------
__device__ __forceinline__ void kan_bases(float x, float bs[6]) {
    const float h = 2.0f / 3.0f;
    float t[10];
#pragma unroll
    for (int j = 0; j < 10; ++j) t[j] = -1.0f + (float)(j - 3) * h;
    float b[9];
#pragma unroll
    for (int j = 0; j < 9; ++j) b[j] = (x >= t[j] && x < t[j + 1]) ? 1.0f : 0.0f;
#pragma unroll
    for (int k = 1; k <= 3; ++k) {
#pragma unroll
        for (int j = 0; j < 9 - k; ++j) {
            float l = (x - t[j])         * (1.0f / (t[j + k]     - t[j]));
            float r = (t[j + k + 1] - x) * (1.0f / (t[j + k + 1] - t[j + 1]));
            b[j] = l * b[j] + r * b[j + 1];
        }
    }
#pragma unroll
    for (int j = 0; j < 6; ++j) bs[j] = b[j];
}

__device__ __forceinline__ float silu_f(float v) {
    return v / (1.0f + expf(-v));
}

// ---------------------------------------------------------------------------
// Activation expansion: x (B x D_IN) -> g_A1 (B x K1), k = j*D_IN + i
// ---------------------------------------------------------------------------
__global__ void expand1_kernel(const float* __restrict__ x) {
    int idx = blockIdx.x * blockDim.x + threadIdx.x;
    if (idx >= B_SZ * D_IN) return;
    int b = idx / D_IN;
    int i = idx - b * D_IN;
    float v = x[idx];
    float bs[6];
    kan_bases(v, bs);
    size_t base = (size_t)b * K1 + i;
    g_A1[base] = __float2half(silu_f(v));
#pragma unroll
    for (int j = 0; j < 6; ++j)
        g_A1[base + (size_t)(j + 1) * D_IN] = __float2half(bs[j]);
}

// ---------------------------------------------------------------------------
// Weight fusion kernels
// ---------------------------------------------------------------------------
__global__ void fusew1_kernel(const float* __restrict__ bw,
                              const float* __restrict__ sw,
                              const float* __restrict__ sc) {
    int idx = blockIdx.x * blockDim.x + threadIdx.x;
    if (idx >= D_HID * D_IN) return;
    int o = idx / D_IN;
    int i = idx - o * D_IN;
    size_t base = (size_t)o * K1 + i;
    g_W1[base] = __float2half(bw[idx]);
    float s = sc[idx];
#pragma unroll
    for (int j = 0; j < 6; ++j)
        g_W1[base + (size_t)(j + 1) * D_IN] = __float2half(sw[(size_t)idx * 6 + j] * s);
}

__global__ void fusew2_kernel(const float* __restrict__ bw,
                              const float* __restrict__ sw,
                              const float* __restrict__ sc) {
    int idx = blockIdx.x * blockDim.x + threadIdx.x;
    if (idx >= N2PAD * D_HID) return;
    int o = idx / D_HID;
    int c = idx - o * D_HID;
    size_t base = (size_t)o * K2 + c;
    if (o < D_OUT) {
        size_t widx = (size_t)o * D_HID + c;
        g_W2[base] = __float2half(bw[widx]);
        float s = sc[widx];
#pragma unroll
        for (int j = 0; j < 6; ++j)
            g_W2[base + (size_t)(j + 1) * D_HID] = __float2half(sw[widx * 6 + j] * s);
    } else {
        g_W2[base] = __float2half(0.0f);
#pragma unroll
        for (int j = 0; j < 6; ++j)
            g_W2[base + (size_t)(j + 1) * D_HID] = __float2half(0.0f);
    }
}

// ---------------------------------------------------------------------------
// LayerNorm over D_HID=512 + expansion into g_A2. One block per row, 256 thr.
// ---------------------------------------------------------------------------
__global__ void ln_expand2_kernel(const float* __restrict__ gamma,
                                  const float* __restrict__ beta) {
    int row = blockIdx.x;
    int t = threadIdx.x;
    const float* hr = g_h + (size_t)row * D_HID;
    float v0 = hr[t];
    float v1 = hr[t + 256];

    __shared__ float red[8];
    float s = v0 + v1;
#pragma unroll
    for (int o = 16; o; o >>= 1) s += __shfl_down_sync(0xffffffffu, s, o);
    if ((t & 31) == 0) red[t >> 5] = s;
    __syncthreads();
    float tot = 0.0f;
#pragma unroll
    for (int i = 0; i < 8; ++i) tot += red[i];
    float mean = tot * (1.0f / (float)D_HID);
    __syncthreads();

    float d0 = v0 - mean, d1 = v1 - mean;
    float q = d0 * d0 + d1 * d1;
#pragma unroll
    for (int o = 16; o; o >>= 1) q += __shfl_down_sync(0xffffffffu, q, o);
    if ((t & 31) == 0) red[t >> 5] = q;
    __syncthreads();
    float qt = 0.0f;
#pragma unroll
    for (int i = 0; i < 8; ++i) qt += red[i];
    float inv = rsqrtf(qt * (1.0f / (float)D_HID) + 1e-5f);

#pragma unroll
    for (int half_idx = 0; half_idx < 2; ++half_idx) {
        int c = t + half_idx * 256;
        float d = (half_idx == 0) ? d0 : d1;
        float y = d * inv * gamma[c] + beta[c];
        float bs[6];
        kan_bases(y, bs);
        size_t base = (size_t)row * K2 + c;
        g_A2[base] = __float2half(silu_f(y));
#pragma unroll
        for (int j = 0; j < 6; ++j)
            g_A2[base + (size_t)(j + 1) * D_HID] = __float2half(bs[j]);
    }
}

// ---------------------------------------------------------------------------
// f16 GEMM: C[M x NV] = A[M x K] * B[N x K]^T   (B stored row-per-output, K-contig)
// mma.sync m16n8k16, block tile 128x64x32, 8 warps (each 32x32), 2-stage cp.async
// ---------------------------------------------------------------------------
#define BM 128
#define BN 64
#define BK 32
#define LDS 40   // BK + 8 skew (halfs)

template <int L>
__global__ __launch_bounds__(256) void gemm_f16(float* __restrict__ Cparam) {
    constexpr int KK = (L == 1) ? K1 : K2;
    constexpr int NV = (L == 1) ? D_HID : D_OUT;
    constexpr int LDC = NV;
    constexpr int KT = KK / BK;

    const __half* __restrict__ A  = (L == 1) ? g_A1 : g_A2;
    const __half* __restrict__ Bm = (L == 1) ? g_W1 : g_W2;
    float* __restrict__ C = (L == 1) ? g_h : Cparam;

    __shared__ __half As[2][BM][LDS];
    __shared__ __half Bs[2][BN][LDS];

    const int tid  = threadIdx.x;
    const int lane = tid & 31;
    const int warp = tid >> 5;
    const int wm = (warp & 3) * 32;   // warp M offset in block
    const int wn = (warp >> 2) * 32;  // warp N offset in block

    const int crow = tid >> 2;        // 0..63 copy row
    const int ccol = (tid & 3) * 8;   // 0,8,16,24 (halfs)

    const int mb = blockIdx.y;
    const int nb = blockIdx.x;

    const __half* Ag0 = A  + (size_t)(mb * BM + crow) * KK + ccol;
    const __half* Ag1 = Ag0 + (size_t)64 * KK;
    const __half* Bg0 = Bm + (size_t)(nb * BN + crow) * KK + ccol;

    const uint32_t sAbase = (uint32_t)__cvta_generic_to_shared(&As[0][0][0]);
    const uint32_t sBbase = (uint32_t)__cvta_generic_to_shared(&Bs[0][0][0]);

    auto issue = [&](int st, int kt) {
        uint32_t a0 = sAbase + (uint32_t)(((st * BM) + crow) * LDS + ccol) * 2u;
        uint32_t a1 = sAbase + (uint32_t)(((st * BM) + crow + 64) * LDS + ccol) * 2u;
        uint32_t b0 = sBbase + (uint32_t)(((st * BN) + crow) * LDS + ccol) * 2u;
        const __half* ga0 = Ag0 + (size_t)kt * BK;
        const __half* ga1 = Ag1 + (size_t)kt * BK;
        const __half* gb0 = Bg0 + (size_t)kt * BK;
        asm volatile("cp.async.cg.shared.global [%0], [%1], 16;\n" :: "r"(a0), "l"(ga0));
        asm volatile("cp.async.cg.shared.global [%0], [%1], 16;\n" :: "r"(a1), "l"(ga1));
        asm volatile("cp.async.cg.shared.global [%0], [%1], 16;\n" :: "r"(b0), "l"(gb0));
        asm volatile("cp.async.commit_group;\n" ::);
    };

    float acc[2][4][4] = {};

    issue(0, 0);

    const int lrow = lane & 15;
    const int lcb  = (lane >> 4) * 8;

    for (int kt = 0; kt < KT; ++kt) {
        asm volatile("cp.async.wait_group 0;\n" ::);
        __syncthreads();
        if (kt + 1 < KT) issue((kt + 1) & 1, kt + 1);
        const int st = kt & 1;
#pragma unroll
        for (int ks = 0; ks < 2; ++ks) {
            uint32_t a[2][4];
            uint32_t bq[2][4];
#pragma unroll
            for (int mt = 0; mt < 2; ++mt) {
                uint32_t addr = sAbase +
                    (uint32_t)(((st * BM) + wm + mt * 16 + lrow) * LDS + ks * 16 + lcb) * 2u;
                asm volatile("ldmatrix.sync.aligned.m8n8.x4.shared.b16 {%0,%1,%2,%3}, [%4];\n"
                             : "=r"(a[mt][0]), "=r"(a[mt][1]), "=r"(a[mt][2]), "=r"(a[mt][3])
                             : "r"(addr));
            }
#pragma unroll
            for (int np = 0; np < 2; ++np) {
                uint32_t addr = sBbase +
                    (uint32_t)(((st * BN) + wn + np * 16 + lrow) * LDS + ks * 16 + lcb) * 2u;
                asm volatile("ldmatrix.sync.aligned.m8n8.x4.shared.b16 {%0,%1,%2,%3}, [%4];\n"
                             : "=r"(bq[np][0]), "=r"(bq[np][1]), "=r"(bq[np][2]), "=r"(bq[np][3])
                             : "r"(addr));
            }
#pragma unroll
            for (int mt = 0; mt < 2; ++mt) {
#pragma unroll
                for (int nt = 0; nt < 4; ++nt) {
                    const int np = nt >> 1, pp = nt & 1;
                    asm volatile(
                        "mma.sync.aligned.m16n8k16.row.col.f32.f16.f16.f32 "
                        "{%0,%1,%2,%3}, {%4,%5,%6,%7}, {%8,%9}, {%0,%1,%2,%3};\n"
                        : "+f"(acc[mt][nt][0]), "+f"(acc[mt][nt][1]),
                          "+f"(acc[mt][nt][2]), "+f"(acc[mt][nt][3])
                        : "r"(a[mt][0]), "r"(a[mt][1]), "r"(a[mt][2]), "r"(a[mt][3]),
                          "r"(bq[np][pp]), "r"(bq[np][pp + 2]));
                }
            }
        }
        __syncthreads();
    }

    // Epilogue: write fp32 C with N guard
    const int gr = lane >> 2;
    const int gc = (lane & 3) * 2;
#pragma unroll
    for (int mt = 0; mt < 2; ++mt) {
#pragma unroll
        for (int nt = 0; nt < 4; ++nt) {
            const int row = mb * BM + wm + mt * 16 + gr;
            const int col = nb * BN + wn + nt * 8 + gc;
            float* cp = C + (size_t)row * LDC;
            if (col < NV)     cp[col]     = acc[mt][nt][0];
            if (col + 1 < NV) cp[col + 1] = acc[mt][nt][1];
            cp += (size_t)8 * LDC;
            if (col < NV)     cp[col]     = acc[mt][nt][2];
            if (col + 1 < NV) cp[col + 1] = acc[mt][nt][3];
        }
    }
}

// ---------------------------------------------------------------------------
// Launch
// ---------------------------------------------------------------------------
extern "C" void kernel_launch(void* const* d_in, const int* in_sizes, int n_in,
                              void* d_out, int out_size) {
    (void)in_sizes; (void)n_in; (void)out_size;
    const float* x   = (const float*)d_in[0];
    const float* bw1 = (const float*)d_in[1];
    const float* sw1 = (const float*)d_in[2];
    const float* sc1 = (const float*)d_in[3];
    const float* ga  = (const float*)d_in[4];
    const float* be  = (const float*)d_in[5];
    const float* bw2 = (const float*)d_in[6];
    const float* sw2 = (const float*)d_in[7];
    const float* sc2 = (const float*)d_in[8];
    float* out = (float*)d_out;

    fusew1_kernel<<<(D_HID * D_IN + 255) / 256, 256>>>(bw1, sw1, sc1);
    fusew2_kernel<<<(N2PAD * D_HID + 255) / 256, 256>>>(bw2, sw2, sc2);
    expand1_kernel<<<(B_SZ * D_IN + 255) / 256, 256>>>(x);

    gemm_f16<1><<<dim3(D_HID / BN, B_SZ / BM), 256>>>(nullptr);

    ln_expand2_kernel<<<B_SZ, 256>>>(ga, be);

    gemm_f16<2><<<dim3(N2PAD / BN, B_SZ / BM), 256>>>(out);
}

// round 3
// speedup vs baseline: 1.0790x; 1.0790x over previous
#include <cuda_runtime.h>
#include <cuda_fp16.h>
#include <stdint.h>
#include <math.h>

// ---------------------------------------------------------------------------
// Problem dims
// ---------------------------------------------------------------------------
#define B_SZ   16384
#define D_IN   1280
#define D_HID  512
#define D_OUT  229
#define K1     (7 * D_IN)    // 8960
#define K2     (7 * D_HID)   // 3584
#define N2PAD  256

// ---------------------------------------------------------------------------
// Scratch
// ---------------------------------------------------------------------------
static __device__ __half g_A1[(size_t)B_SZ * K1];
static __device__ __half g_W1[(size_t)D_HID * K1];
static __device__ float  g_h [(size_t)B_SZ * D_HID];
static __device__ __half g_A2[(size_t)B_SZ * K2];
static __device__ __half g_W2[(size_t)N2PAD * K2];

// ---------------------------------------------------------------------------
// B-spline bases + silu (matches reference recursion)
// ---------------------------------------------------------------------------
__device__ __forceinline__ void kan_bases(float x, float bs[6]) {
    const float h = 2.0f / 3.0f;
    float t[10];
#pragma unroll
    for (int j = 0; j < 10; ++j) t[j] = -1.0f + (float)(j - 3) * h;
    float b[9];
#pragma unroll
    for (int j = 0; j < 9; ++j) b[j] = (x >= t[j] && x < t[j + 1]) ? 1.0f : 0.0f;
#pragma unroll
    for (int k = 1; k <= 3; ++k) {
#pragma unroll
        for (int j = 0; j < 9 - k; ++j) {
            float l = (x - t[j])         * (1.0f / (t[j + k]     - t[j]));
            float r = (t[j + k + 1] - x) * (1.0f / (t[j + k + 1] - t[j + 1]));
            b[j] = l * b[j] + r * b[j + 1];
        }
    }
#pragma unroll
    for (int j = 0; j < 6; ++j) bs[j] = b[j];
}

__device__ __forceinline__ float silu_f(float v) { return v / (1.0f + expf(-v)); }

// ---------------------------------------------------------------------------
// Expansion / weight fusion / LN kernels
// ---------------------------------------------------------------------------
__global__ void expand1_kernel(const float* __restrict__ x) {
    int idx = blockIdx.x * blockDim.x + threadIdx.x;
    if (idx >= B_SZ * D_IN) return;
    int b = idx / D_IN;
    int i = idx - b * D_IN;
    float v = x[idx];
    float bs[6];
    kan_bases(v, bs);
    size_t base = (size_t)b * K1 + i;
    g_A1[base] = __float2half(silu_f(v));
#pragma unroll
    for (int j = 0; j < 6; ++j)
        g_A1[base + (size_t)(j + 1) * D_IN] = __float2half(bs[j]);
}

__global__ void fusew1_kernel(const float* __restrict__ bw,
                              const float* __restrict__ sw,
                              const float* __restrict__ sc) {
    int idx = blockIdx.x * blockDim.x + threadIdx.x;
    if (idx >= D_HID * D_IN) return;
    int o = idx / D_IN;
    int i = idx - o * D_IN;
    size_t base = (size_t)o * K1 + i;
    g_W1[base] = __float2half(bw[idx]);
    float s = sc[idx];
#pragma unroll
    for (int j = 0; j < 6; ++j)
        g_W1[base + (size_t)(j + 1) * D_IN] = __float2half(sw[(size_t)idx * 6 + j] * s);
}

__global__ void fusew2_kernel(const float* __restrict__ bw,
                              const float* __restrict__ sw,
                              const float* __restrict__ sc) {
    int idx = blockIdx.x * blockDim.x + threadIdx.x;
    if (idx >= N2PAD * D_HID) return;
    int o = idx / D_HID;
    int c = idx - o * D_HID;
    size_t base = (size_t)o * K2 + c;
    if (o < D_OUT) {
        size_t widx = (size_t)o * D_HID + c;
        g_W2[base] = __float2half(bw[widx]);
        float s = sc[widx];
#pragma unroll
        for (int j = 0; j < 6; ++j)
            g_W2[base + (size_t)(j + 1) * D_HID] = __float2half(sw[widx * 6 + j] * s);
    } else {
        g_W2[base] = __float2half(0.0f);
#pragma unroll
        for (int j = 0; j < 6; ++j)
            g_W2[base + (size_t)(j + 1) * D_HID] = __float2half(0.0f);
    }
}

__global__ void ln_expand2_kernel(const float* __restrict__ gamma,
                                  const float* __restrict__ beta) {
    int row = blockIdx.x;
    int t = threadIdx.x;
    const float* hr = g_h + (size_t)row * D_HID;
    float v0 = hr[t];
    float v1 = hr[t + 256];

    __shared__ float red[8];
    float s = v0 + v1;
#pragma unroll
    for (int o = 16; o; o >>= 1) s += __shfl_down_sync(0xffffffffu, s, o);
    if ((t & 31) == 0) red[t >> 5] = s;
    __syncthreads();
    float tot = 0.0f;
#pragma unroll
    for (int i = 0; i < 8; ++i) tot += red[i];
    float mean = tot * (1.0f / (float)D_HID);
    __syncthreads();

    float d0 = v0 - mean, d1 = v1 - mean;
    float q = d0 * d0 + d1 * d1;
#pragma unroll
    for (int o = 16; o; o >>= 1) q += __shfl_down_sync(0xffffffffu, q, o);
    if ((t & 31) == 0) red[t >> 5] = q;
    __syncthreads();
    float qt = 0.0f;
#pragma unroll
    for (int i = 0; i < 8; ++i) qt += red[i];
    float inv = rsqrtf(qt * (1.0f / (float)D_HID) + 1e-5f);

#pragma unroll
    for (int hx = 0; hx < 2; ++hx) {
        int c = t + hx * 256;
        float d = (hx == 0) ? d0 : d1;
        float y = d * inv * gamma[c] + beta[c];
        float bs[6];
        kan_bases(y, bs);
        size_t base = (size_t)row * K2 + c;
        g_A2[base] = __float2half(silu_f(y));
#pragma unroll
        for (int j = 0; j < 6; ++j)
            g_A2[base + (size_t)(j + 1) * D_HID] = __float2half(bs[j]);
    }
}

// ---------------------------------------------------------------------------
// HMMA GEMM: C[M x NV] = A[M x K] * B[N x K]^T  (f16 in, fp32 out)
// Block 256x128x32, 512 threads (16 warps = 4M x 4N), warp tile 64x32.
// 4-stage cp.async ring, one __syncthreads per K-step.
// SMEM rows padded to 80B: ldmatrix row bank = 20*row mod 32 (conflict-free).
// ---------------------------------------------------------------------------
#define BM 256
#define BN 128
#define BK 32
#define ROWB 80u                       // bytes per smem row (32 halfs + 8 pad)
#define STG_B (uint32_t)((BM + BN) * ROWB)   // 30720 B per stage
#define NSTG 4

template <int L>
__global__ __launch_bounds__(512, 1) void gemm_hmma(float* __restrict__ Cparam) {
    constexpr int KK = (L == 1) ? K1 : K2;
    constexpr int NV = (L == 1) ? D_HID : D_OUT;
    constexpr int KT = KK / BK;

    const __half* __restrict__ A  = (L == 1) ? g_A1 : g_A2;
    const __half* __restrict__ Bw = (L == 1) ? g_W1 : g_W2;
    float* __restrict__ C         = (L == 1) ? g_h  : Cparam;

    extern __shared__ __half smh[];
    const uint32_t sbase = (uint32_t)__cvta_generic_to_shared(smh);

    const int tid  = threadIdx.x;
    const int warp = tid >> 5;
    const int lane = tid & 31;
    const int wm = (warp & 3) * 64;
    const int wn = (warp >> 2) * 32;
    const int mb = blockIdx.y;
    const int nb = blockIdx.x;

    const __half* Abase = A  + (size_t)(mb * BM) * KK;
    const __half* Bbase = Bw + (size_t)(nb * BN) * KK;

    auto issue = [&](int kt) {
        const uint32_t sb = sbase + (uint32_t)(kt & (NSTG - 1)) * STG_B;
        // A: 256 rows x 4 chunks of 16B
#pragma unroll
        for (int i = 0; i < 2; ++i) {
            const int idx = tid + i * 512;
            const int r = idx >> 2, c = idx & 3;
            const void* src = Abase + (size_t)r * KK + kt * BK + c * 8;
            const uint32_t dst = sb + (uint32_t)r * ROWB + (uint32_t)c * 16u;
            asm volatile("cp.async.cg.shared.global [%0], [%1], 16;"
                         :: "r"(dst), "l"(src));
        }
        // B: 128 rows x 4 chunks
        {
            const int r = tid >> 2, c = tid & 3;
            const void* src = Bbase + (size_t)r * KK + kt * BK + c * 8;
            const uint32_t dst = sb + (uint32_t)BM * ROWB + (uint32_t)r * ROWB + (uint32_t)c * 16u;
            asm volatile("cp.async.cg.shared.global [%0], [%1], 16;"
                         :: "r"(dst), "l"(src));
        }
        asm volatile("cp.async.commit_group;" ::: "memory");
    };

    float acc[4][4][4] = {};

    issue(0); issue(1); issue(2);

    const int lrow = lane & 15;
    const int lcb  = (lane >> 4) * 8;

#pragma unroll 1
    for (int kt = 0; kt < KT; ++kt) {
        if (kt + 3 < KT) asm volatile("cp.async.wait_group 2;" ::: "memory");
        else             asm volatile("cp.async.wait_group 0;" ::: "memory");
        __syncthreads();
        if (kt + 3 < KT) issue(kt + 3);

        const uint32_t sb = sbase + (uint32_t)(kt & (NSTG - 1)) * STG_B;
#pragma unroll
        for (int ks = 0; ks < 2; ++ks) {
            uint32_t a[4][4];
            uint32_t bq[2][4];
#pragma unroll
            for (int mt = 0; mt < 4; ++mt) {
                const uint32_t addr = sb + (uint32_t)(wm + mt * 16 + lrow) * ROWB
                                    + (uint32_t)(ks * 16 + lcb) * 2u;
                asm volatile("ldmatrix.sync.aligned.m8n8.x4.shared.b16 {%0,%1,%2,%3}, [%4];"
                             : "=r"(a[mt][0]), "=r"(a[mt][1]), "=r"(a[mt][2]), "=r"(a[mt][3])
                             : "r"(addr));
            }
#pragma unroll
            for (int np = 0; np < 2; ++np) {
                const uint32_t addr = sb + (uint32_t)BM * ROWB
                                    + (uint32_t)(wn + np * 16 + lrow) * ROWB
                                    + (uint32_t)(ks * 16 + lcb) * 2u;
                asm volatile("ldmatrix.sync.aligned.m8n8.x4.shared.b16 {%0,%1,%2,%3}, [%4];"
                             : "=r"(bq[np][0]), "=r"(bq[np][1]), "=r"(bq[np][2]), "=r"(bq[np][3])
                             : "r"(addr));
            }
#pragma unroll
            for (int mt = 0; mt < 4; ++mt) {
#pragma unroll
                for (int nt = 0; nt < 4; ++nt) {
                    const int np = nt >> 1, pp = nt & 1;
                    asm volatile(
                        "mma.sync.aligned.m16n8k16.row.col.f32.f16.f16.f32 "
                        "{%0,%1,%2,%3}, {%4,%5,%6,%7}, {%8,%9}, {%0,%1,%2,%3};"
                        : "+f"(acc[mt][nt][0]), "+f"(acc[mt][nt][1]),
                          "+f"(acc[mt][nt][2]), "+f"(acc[mt][nt][3])
                        : "r"(a[mt][0]), "r"(a[mt][1]), "r"(a[mt][2]), "r"(a[mt][3]),
                          "r"(bq[np][pp]), "r"(bq[np][pp + 2]));
                }
            }
        }
    }

    // ---- epilogue ----
    const int gr = lane >> 2;
    const int gc = (lane & 3) * 2;
#pragma unroll
    for (int mt = 0; mt < 4; ++mt) {
#pragma unroll
        for (int nt = 0; nt < 4; ++nt) {
            const int row = mb * BM + wm + mt * 16 + gr;
            const int col = nb * BN + wn + nt * 8 + gc;
            float* cp = C + (size_t)row * NV;
            if (NV % BN == 0) {
                cp[col]     = acc[mt][nt][0];
                cp[col + 1] = acc[mt][nt][1];
                cp += (size_t)8 * NV;
                cp[col]     = acc[mt][nt][2];
                cp[col + 1] = acc[mt][nt][3];
            } else {
                if (col < NV)     cp[col]     = acc[mt][nt][0];
                if (col + 1 < NV) cp[col + 1] = acc[mt][nt][1];
                cp += (size_t)8 * NV;
                if (col < NV)     cp[col]     = acc[mt][nt][2];
                if (col + 1 < NV) cp[col + 1] = acc[mt][nt][3];
            }
        }
    }
}

// ---------------------------------------------------------------------------
// Launch
// ---------------------------------------------------------------------------
#define GEMM_SMEM (NSTG * (int)STG_B)   // 122880 B

extern "C" void kernel_launch(void* const* d_in, const int* in_sizes, int n_in,
                              void* d_out, int out_size) {
    (void)in_sizes; (void)n_in; (void)out_size;
    const float* x   = (const float*)d_in[0];
    const float* bw1 = (const float*)d_in[1];
    const float* sw1 = (const float*)d_in[2];
    const float* sc1 = (const float*)d_in[3];
    const float* ga  = (const float*)d_in[4];
    const float* be  = (const float*)d_in[5];
    const float* bw2 = (const float*)d_in[6];
    const float* sw2 = (const float*)d_in[7];
    const float* sc2 = (const float*)d_in[8];
    float* out = (float*)d_out;

    cudaFuncSetAttribute(gemm_hmma<1>,
                         cudaFuncAttributeMaxDynamicSharedMemorySize, GEMM_SMEM);
    cudaFuncSetAttribute(gemm_hmma<2>,
                         cudaFuncAttributeMaxDynamicSharedMemorySize, GEMM_SMEM);

    fusew1_kernel<<<(D_HID * D_IN + 255) / 256, 256>>>(bw1, sw1, sc1);
    fusew2_kernel<<<(N2PAD * D_HID + 255) / 256, 256>>>(bw2, sw2, sc2);
    expand1_kernel<<<(B_SZ * D_IN + 255) / 256, 256>>>(x);

    // GEMM1: N blocks = 512/128 = 4, M blocks = 16384/256 = 64  -> 256 CTAs
    gemm_hmma<1><<<dim3(4, 64), 512, GEMM_SMEM>>>(nullptr);

    ln_expand2_kernel<<<B_SZ, 256>>>(ga, be);

    // GEMM2: N blocks = 256/128 = 2, M blocks = 64 -> 128 CTAs
    gemm_hmma<2><<<dim3(2, 64), 512, GEMM_SMEM>>>(out);
}

// round 4
// speedup vs baseline: 1.1210x; 1.0388x over previous
#include <cuda_runtime.h>
#include <cuda_fp16.h>
#include <stdint.h>
#include <math.h>

// ---------------------------------------------------------------------------
// Problem dims
// ---------------------------------------------------------------------------
#define B_SZ   16384
#define D_IN   1280
#define D_HID  512
#define D_OUT  229
#define K1     (7 * D_IN)    // 8960
#define K2     (7 * D_HID)   // 3584
#define N2PAD  256

// ---------------------------------------------------------------------------
// Scratch
// ---------------------------------------------------------------------------
static __device__ __half g_A1[(size_t)B_SZ * K1];
static __device__ __half g_W1[(size_t)D_HID * K1];
static __device__ float  g_h [(size_t)B_SZ * D_HID];
static __device__ __half g_A2[(size_t)B_SZ * K2];
static __device__ __half g_W2[(size_t)N2PAD * K2];

// ---------------------------------------------------------------------------
// B-spline bases + silu (matches reference recursion)
// ---------------------------------------------------------------------------
__device__ __forceinline__ void kan_bases(float x, float bs[6]) {
    const float h = 2.0f / 3.0f;
    float t[10];
#pragma unroll
    for (int j = 0; j < 10; ++j) t[j] = -1.0f + (float)(j - 3) * h;
    float b[9];
#pragma unroll
    for (int j = 0; j < 9; ++j) b[j] = (x >= t[j] && x < t[j + 1]) ? 1.0f : 0.0f;
#pragma unroll
    for (int k = 1; k <= 3; ++k) {
#pragma unroll
        for (int j = 0; j < 9 - k; ++j) {
            float l = (x - t[j])         * (1.0f / (t[j + k]     - t[j]));
            float r = (t[j + k + 1] - x) * (1.0f / (t[j + k + 1] - t[j + 1]));
            b[j] = l * b[j] + r * b[j + 1];
        }
    }
#pragma unroll
    for (int j = 0; j < 6; ++j) bs[j] = b[j];
}

__device__ __forceinline__ float silu_f(float v) { return v / (1.0f + expf(-v)); }

// ---------------------------------------------------------------------------
// Expansion / weight fusion / LN kernels
// ---------------------------------------------------------------------------
__global__ void expand1_kernel(const float* __restrict__ x) {
    int idx = blockIdx.x * blockDim.x + threadIdx.x;
    if (idx >= B_SZ * D_IN) return;
    int b = idx / D_IN;
    int i = idx - b * D_IN;
    float v = x[idx];
    float bs[6];
    kan_bases(v, bs);
    size_t base = (size_t)b * K1 + i;
    g_A1[base] = __float2half(silu_f(v));
#pragma unroll
    for (int j = 0; j < 6; ++j)
        g_A1[base + (size_t)(j + 1) * D_IN] = __float2half(bs[j]);
}

__global__ void fusew1_kernel(const float* __restrict__ bw,
                              const float* __restrict__ sw,
                              const float* __restrict__ sc) {
    int idx = blockIdx.x * blockDim.x + threadIdx.x;
    if (idx >= D_HID * D_IN) return;
    int o = idx / D_IN;
    int i = idx - o * D_IN;
    size_t base = (size_t)o * K1 + i;
    g_W1[base] = __float2half(bw[idx]);
    float s = sc[idx];
#pragma unroll
    for (int j = 0; j < 6; ++j)
        g_W1[base + (size_t)(j + 1) * D_IN] = __float2half(sw[(size_t)idx * 6 + j] * s);
}

__global__ void fusew2_kernel(const float* __restrict__ bw,
                              const float* __restrict__ sw,
                              const float* __restrict__ sc) {
    int idx = blockIdx.x * blockDim.x + threadIdx.x;
    if (idx >= N2PAD * D_HID) return;
    int o = idx / D_HID;
    int c = idx - o * D_HID;
    size_t base = (size_t)o * K2 + c;
    if (o < D_OUT) {
        size_t widx = (size_t)o * D_HID + c;
        g_W2[base] = __float2half(bw[widx]);
        float s = sc[widx];
#pragma unroll
        for (int j = 0; j < 6; ++j)
            g_W2[base + (size_t)(j + 1) * D_HID] = __float2half(sw[widx * 6 + j] * s);
    } else {
        g_W2[base] = __float2half(0.0f);
#pragma unroll
        for (int j = 0; j < 6; ++j)
            g_W2[base + (size_t)(j + 1) * D_HID] = __float2half(0.0f);
    }
}

__global__ void ln_expand2_kernel(const float* __restrict__ gamma,
                                  const float* __restrict__ beta) {
    int row = blockIdx.x;
    int t = threadIdx.x;
    const float* hr = g_h + (size_t)row * D_HID;
    float v0 = hr[t];
    float v1 = hr[t + 256];

    __shared__ float red[8];
    float s = v0 + v1;
#pragma unroll
    for (int o = 16; o; o >>= 1) s += __shfl_down_sync(0xffffffffu, s, o);
    if ((t & 31) == 0) red[t >> 5] = s;
    __syncthreads();
    float tot = 0.0f;
#pragma unroll
    for (int i = 0; i < 8; ++i) tot += red[i];
    float mean = tot * (1.0f / (float)D_HID);
    __syncthreads();

    float d0 = v0 - mean, d1 = v1 - mean;
    float q = d0 * d0 + d1 * d1;
#pragma unroll
    for (int o = 16; o; o >>= 1) q += __shfl_down_sync(0xffffffffu, q, o);
    if ((t & 31) == 0) red[t >> 5] = q;
    __syncthreads();
    float qt = 0.0f;
#pragma unroll
    for (int i = 0; i < 8; ++i) qt += red[i];
    float inv = rsqrtf(qt * (1.0f / (float)D_HID) + 1e-5f);

#pragma unroll
    for (int hx = 0; hx < 2; ++hx) {
        int c = t + hx * 256;
        float d = (hx == 0) ? d0 : d1;
        float y = d * inv * gamma[c] + beta[c];
        float bs[6];
        kan_bases(y, bs);
        size_t base = (size_t)row * K2 + c;
        g_A2[base] = __float2half(silu_f(y));
#pragma unroll
        for (int j = 0; j < 6; ++j)
            g_A2[base + (size_t)(j + 1) * D_HID] = __float2half(bs[j]);
    }
}

// ---------------------------------------------------------------------------
// HMMA GEMM: C[M x NV] = A[M x K] * B[N x K]^T  (f16 in, fp32 out)
// Block 128x128x64, 256 threads (8 warps = 2M x 4N), warp tile 64x32.
// 3-stage cp.async ring, one __syncthreads per 64-wide K-step.
// Designed for 2 CTAs/SM: smem 108KB/CTA, regs <= 128 (launch_bounds).
// SMEM rows: 128B data + 16B pad = 144B -> row r starts at bank 4r mod 32
// (all ldmatrix / cp.async phases at their bank-bandwidth floor).
// ---------------------------------------------------------------------------
#define BM 128
#define BN 128
#define BK 64
#define ROWB 144u
#define STG_B (uint32_t)((BM + BN) * ROWB)   // 36864 B
#define NSTG 3

template <int L>
__global__ __launch_bounds__(256, 2) void gemm_hmma(float* __restrict__ Cparam) {
    constexpr int KK = (L == 1) ? K1 : K2;
    constexpr int NV = (L == 1) ? D_HID : D_OUT;
    constexpr int KT = KK / BK;

    const __half* __restrict__ A  = (L == 1) ? g_A1 : g_A2;
    const __half* __restrict__ Bw = (L == 1) ? g_W1 : g_W2;
    float* __restrict__ C         = (L == 1) ? g_h  : Cparam;

    extern __shared__ __half smh[];
    const uint32_t sbase = (uint32_t)__cvta_generic_to_shared(smh);

    const int tid  = threadIdx.x;
    const int warp = tid >> 5;
    const int lane = tid & 31;
    const int wm = (warp & 1) * 64;
    const int wn = (warp >> 1) * 32;
    const int mb = blockIdx.y;
    const int nb = blockIdx.x;

    const __half* Abase = A  + (size_t)(mb * BM) * KK;
    const __half* Bbase = Bw + (size_t)(nb * BN) * KK;

    auto issue = [&](int kt) {
        const uint32_t sb = sbase + (uint32_t)(kt % NSTG) * STG_B;
        // A: 128 rows x 8 chunks of 16B = 1024 chunks; 4 per thread
#pragma unroll
        for (int i = 0; i < 4; ++i) {
            const int idx = tid + i * 256;
            const int r = idx >> 3, c = idx & 7;
            const void* src = Abase + (size_t)r * KK + kt * BK + c * 8;
            const uint32_t dst = sb + (uint32_t)r * ROWB + (uint32_t)c * 16u;
            asm volatile("cp.async.cg.shared.global [%0], [%1], 16;"
                         :: "r"(dst), "l"(src));
        }
        // B: 128 rows x 8 chunks
#pragma unroll
        for (int i = 0; i < 4; ++i) {
            const int idx = tid + i * 256;
            const int r = idx >> 3, c = idx & 7;
            const void* src = Bbase + (size_t)r * KK + kt * BK + c * 8;
            const uint32_t dst = sb + (uint32_t)BM * ROWB
                               + (uint32_t)r * ROWB + (uint32_t)c * 16u;
            asm volatile("cp.async.cg.shared.global [%0], [%1], 16;"
                         :: "r"(dst), "l"(src));
        }
        asm volatile("cp.async.commit_group;" ::: "memory");
    };

    float acc[4][4][4] = {};

    issue(0); issue(1);

    const int lrow = lane & 15;
    const int lcb  = (lane >> 4) * 8;

#pragma unroll 1
    for (int kt = 0; kt < KT; ++kt) {
        if (kt + 1 < KT) asm volatile("cp.async.wait_group 1;" ::: "memory");
        else             asm volatile("cp.async.wait_group 0;" ::: "memory");
        __syncthreads();
        if (kt + 2 < KT) issue(kt + 2);

        const uint32_t sb = sbase + (uint32_t)(kt % NSTG) * STG_B;
#pragma unroll
        for (int ks = 0; ks < 4; ++ks) {
            uint32_t a[4][4];
            uint32_t bq[2][4];
#pragma unroll
            for (int mt = 0; mt < 4; ++mt) {
                const uint32_t addr = sb + (uint32_t)(wm + mt * 16 + lrow) * ROWB
                                    + (uint32_t)(ks * 16 + lcb) * 2u;
                asm volatile("ldmatrix.sync.aligned.m8n8.x4.shared.b16 {%0,%1,%2,%3}, [%4];"
                             : "=r"(a[mt][0]), "=r"(a[mt][1]), "=r"(a[mt][2]), "=r"(a[mt][3])
                             : "r"(addr));
            }
#pragma unroll
            for (int np = 0; np < 2; ++np) {
                const uint32_t addr = sb + (uint32_t)BM * ROWB
                                    + (uint32_t)(wn + np * 16 + lrow) * ROWB
                                    + (uint32_t)(ks * 16 + lcb) * 2u;
                asm volatile("ldmatrix.sync.aligned.m8n8.x4.shared.b16 {%0,%1,%2,%3}, [%4];"
                             : "=r"(bq[np][0]), "=r"(bq[np][1]), "=r"(bq[np][2]), "=r"(bq[np][3])
                             : "r"(addr));
            }
#pragma unroll
            for (int mt = 0; mt < 4; ++mt) {
#pragma unroll
                for (int nt = 0; nt < 4; ++nt) {
                    const int np = nt >> 1, pp = nt & 1;
                    asm volatile(
                        "mma.sync.aligned.m16n8k16.row.col.f32.f16.f16.f32 "
                        "{%0,%1,%2,%3}, {%4,%5,%6,%7}, {%8,%9}, {%0,%1,%2,%3};"
                        : "+f"(acc[mt][nt][0]), "+f"(acc[mt][nt][1]),
                          "+f"(acc[mt][nt][2]), "+f"(acc[mt][nt][3])
                        : "r"(a[mt][0]), "r"(a[mt][1]), "r"(a[mt][2]), "r"(a[mt][3]),
                          "r"(bq[np][pp]), "r"(bq[np][pp + 2]));
                }
            }
        }
    }

    // ---- epilogue ----
    const int gr = lane >> 2;
    const int gc = (lane & 3) * 2;
#pragma unroll
    for (int mt = 0; mt < 4; ++mt) {
#pragma unroll
        for (int nt = 0; nt < 4; ++nt) {
            const int row = mb * BM + wm + mt * 16 + gr;
            const int col = nb * BN + wn + nt * 8 + gc;
            float* cp = C + (size_t)row * NV;
            if (NV % BN == 0) {
                cp[col]     = acc[mt][nt][0];
                cp[col + 1] = acc[mt][nt][1];
                cp += (size_t)8 * NV;
                cp[col]     = acc[mt][nt][2];
                cp[col + 1] = acc[mt][nt][3];
            } else {
                if (col < NV)     cp[col]     = acc[mt][nt][0];
                if (col + 1 < NV) cp[col + 1] = acc[mt][nt][1];
                cp += (size_t)8 * NV;
                if (col < NV)     cp[col]     = acc[mt][nt][2];
                if (col + 1 < NV) cp[col + 1] = acc[mt][nt][3];
            }
        }
    }
}

// ---------------------------------------------------------------------------
// Launch
// ---------------------------------------------------------------------------
#define GEMM_SMEM (NSTG * (int)STG_B)   // 110592 B

extern "C" void kernel_launch(void* const* d_in, const int* in_sizes, int n_in,
                              void* d_out, int out_size) {
    (void)in_sizes; (void)n_in; (void)out_size;
    const float* x   = (const float*)d_in[0];
    const float* bw1 = (const float*)d_in[1];
    const float* sw1 = (const float*)d_in[2];
    const float* sc1 = (const float*)d_in[3];
    const float* ga  = (const float*)d_in[4];
    const float* be  = (const float*)d_in[5];
    const float* bw2 = (const float*)d_in[6];
    const float* sw2 = (const float*)d_in[7];
    const float* sc2 = (const float*)d_in[8];
    float* out = (float*)d_out;

    cudaFuncSetAttribute(gemm_hmma<1>,
                         cudaFuncAttributeMaxDynamicSharedMemorySize, GEMM_SMEM);
    cudaFuncSetAttribute(gemm_hmma<2>,
                         cudaFuncAttributeMaxDynamicSharedMemorySize, GEMM_SMEM);

    fusew1_kernel<<<(D_HID * D_IN + 255) / 256, 256>>>(bw1, sw1, sc1);
    fusew2_kernel<<<(N2PAD * D_HID + 255) / 256, 256>>>(bw2, sw2, sc2);
    expand1_kernel<<<(B_SZ * D_IN + 255) / 256, 256>>>(x);

    // GEMM1: N blocks = 512/128 = 4, M blocks = 16384/128 = 128 -> 512 CTAs
    gemm_hmma<1><<<dim3(4, 128), 256, GEMM_SMEM>>>(nullptr);

    ln_expand2_kernel<<<B_SZ, 256>>>(ga, be);

    // GEMM2: N blocks = 256/128 = 2, M blocks = 128 -> 256 CTAs
    gemm_hmma<2><<<dim3(2, 128), 256, GEMM_SMEM>>>(out);
}

// round 5
// speedup vs baseline: 1.1727x; 1.0462x over previous
#include <cuda_runtime.h>
#include <cuda_fp16.h>
#include <stdint.h>
#include <math.h>

// ---------------------------------------------------------------------------
// Problem dims
// ---------------------------------------------------------------------------
#define B_SZ   16384
#define D_IN   1280
#define D_HID  512
#define D_OUT  229
#define K1     (7 * D_IN)    // 8960
#define K2     (7 * D_HID)   // 3584
#define N2PAD  256

// ---------------------------------------------------------------------------
// Scratch
// ---------------------------------------------------------------------------
static __device__ __half g_A1[(size_t)B_SZ * K1];
static __device__ __half g_W1[(size_t)D_HID * K1];
static __device__ float  g_h [(size_t)B_SZ * D_HID];
static __device__ __half g_A2[(size_t)B_SZ * K2];
static __device__ __half g_W2[(size_t)N2PAD * K2];

// ---------------------------------------------------------------------------
// B-spline bases + silu (matches reference recursion)
// ---------------------------------------------------------------------------
__device__ __forceinline__ void kan_bases(float x, float bs[6]) {
    const float h = 2.0f / 3.0f;
    float t[10];
#pragma unroll
    for (int j = 0; j < 10; ++j) t[j] = -1.0f + (float)(j - 3) * h;
    float b[9];
#pragma unroll
    for (int j = 0; j < 9; ++j) b[j] = (x >= t[j] && x < t[j + 1]) ? 1.0f : 0.0f;
#pragma unroll
    for (int k = 1; k <= 3; ++k) {
#pragma unroll
        for (int j = 0; j < 9 - k; ++j) {
            float l = (x - t[j])         * (1.0f / (t[j + k]     - t[j]));
            float r = (t[j + k + 1] - x) * (1.0f / (t[j + k + 1] - t[j + 1]));
            b[j] = l * b[j] + r * b[j + 1];
        }
    }
#pragma unroll
    for (int j = 0; j < 6; ++j) bs[j] = b[j];
}

__device__ __forceinline__ float silu_f(float v) { return v / (1.0f + expf(-v)); }

// ---------------------------------------------------------------------------
// Expansion / weight fusion / LN kernels
// ---------------------------------------------------------------------------
__global__ void expand1_kernel(const float* __restrict__ x) {
    int idx = blockIdx.x * blockDim.x + threadIdx.x;
    if (idx >= B_SZ * D_IN) return;
    int b = idx / D_IN;
    int i = idx - b * D_IN;
    float v = x[idx];
    float bs[6];
    kan_bases(v, bs);
    size_t base = (size_t)b * K1 + i;
    g_A1[base] = __float2half(silu_f(v));
#pragma unroll
    for (int j = 0; j < 6; ++j)
        g_A1[base + (size_t)(j + 1) * D_IN] = __float2half(bs[j]);
}

__global__ void fusew1_kernel(const float* __restrict__ bw,
                              const float* __restrict__ sw,
                              const float* __restrict__ sc) {
    int idx = blockIdx.x * blockDim.x + threadIdx.x;
    if (idx >= D_HID * D_IN) return;
    int o = idx / D_IN;
    int i = idx - o * D_IN;
    size_t base = (size_t)o * K1 + i;
    g_W1[base] = __float2half(bw[idx]);
    float s = sc[idx];
#pragma unroll
    for (int j = 0; j < 6; ++j)
        g_W1[base + (size_t)(j + 1) * D_IN] = __float2half(sw[(size_t)idx * 6 + j] * s);
}

__global__ void fusew2_kernel(const float* __restrict__ bw,
                              const float* __restrict__ sw,
                              const float* __restrict__ sc) {
    int idx = blockIdx.x * blockDim.x + threadIdx.x;
    if (idx >= N2PAD * D_HID) return;
    int o = idx / D_HID;
    int c = idx - o * D_HID;
    size_t base = (size_t)o * K2 + c;
    if (o < D_OUT) {
        size_t widx = (size_t)o * D_HID + c;
        g_W2[base] = __float2half(bw[widx]);
        float s = sc[widx];
#pragma unroll
        for (int j = 0; j < 6; ++j)
            g_W2[base + (size_t)(j + 1) * D_HID] = __float2half(sw[widx * 6 + j] * s);
    } else {
        g_W2[base] = __float2half(0.0f);
#pragma unroll
        for (int j = 0; j < 6; ++j)
            g_W2[base + (size_t)(j + 1) * D_HID] = __float2half(0.0f);
    }
}

__global__ void ln_expand2_kernel(const float* __restrict__ gamma,
                                  const float* __restrict__ beta) {
    int row = blockIdx.x;
    int t = threadIdx.x;
    const float* hr = g_h + (size_t)row * D_HID;
    float v0 = hr[t];
    float v1 = hr[t + 256];

    __shared__ float red[8];
    float s = v0 + v1;
#pragma unroll
    for (int o = 16; o; o >>= 1) s += __shfl_down_sync(0xffffffffu, s, o);
    if ((t & 31) == 0) red[t >> 5] = s;
    __syncthreads();
    float tot = 0.0f;
#pragma unroll
    for (int i = 0; i < 8; ++i) tot += red[i];
    float mean = tot * (1.0f / (float)D_HID);
    __syncthreads();

    float d0 = v0 - mean, d1 = v1 - mean;
    float q = d0 * d0 + d1 * d1;
#pragma unroll
    for (int o = 16; o; o >>= 1) q += __shfl_down_sync(0xffffffffu, q, o);
    if ((t & 31) == 0) red[t >> 5] = q;
    __syncthreads();
    float qt = 0.0f;
#pragma unroll
    for (int i = 0; i < 8; ++i) qt += red[i];
    float inv = rsqrtf(qt * (1.0f / (float)D_HID) + 1e-5f);

#pragma unroll
    for (int hx = 0; hx < 2; ++hx) {
        int c = t + hx * 256;
        float d = (hx == 0) ? d0 : d1;
        float y = d * inv * gamma[c] + beta[c];
        float bs[6];
        kan_bases(y, bs);
        size_t base = (size_t)row * K2 + c;
        g_A2[base] = __float2half(silu_f(y));
#pragma unroll
        for (int j = 0; j < 6; ++j)
            g_A2[base + (size_t)(j + 1) * D_HID] = __float2half(bs[j]);
    }
}

// ---------------------------------------------------------------------------
// HMMA GEMM: C[M x NV] = A[M x K] * B[N x K]^T  (f16 in, fp32 out)
// Block 128x128x64, 512 threads (16 warps = 4M x 4N), warp tile 32x32.
// => 32 warps/SM at 2 CTAs/SM (8 per SMSP) for latency hiding.
// 3-stage cp.async ring; regs <= 64/thread (acc 32 + frags 16).
// SMEM rows: 128B data + 16B pad = 144B (conflict-free ldmatrix phases).
// ---------------------------------------------------------------------------
#define BM 128
#define BN 128
#define BK 64
#define ROWB 144u
#define STG_B (uint32_t)((BM + BN) * ROWB)   // 36864 B
#define NSTG 3

template <int L>
__global__ __launch_bounds__(512, 2) void gemm_hmma(float* __restrict__ Cparam) {
    constexpr int KK = (L == 1) ? K1 : K2;
    constexpr int NV = (L == 1) ? D_HID : D_OUT;
    constexpr int KT = KK / BK;

    const __half* __restrict__ A  = (L == 1) ? g_A1 : g_A2;
    const __half* __restrict__ Bw = (L == 1) ? g_W1 : g_W2;
    float* __restrict__ C         = (L == 1) ? g_h  : Cparam;

    extern __shared__ __half smh[];
    const uint32_t sbase = (uint32_t)__cvta_generic_to_shared(smh);

    const int tid  = threadIdx.x;
    const int warp = tid >> 5;
    const int lane = tid & 31;
    const int wm = (warp & 3) * 32;
    const int wn = (warp >> 2) * 32;
    const int mb = blockIdx.y;
    const int nb = blockIdx.x;

    const __half* Abase = A  + (size_t)(mb * BM) * KK;
    const __half* Bbase = Bw + (size_t)(nb * BN) * KK;

    auto issue = [&](int kt) {
        const uint32_t sb = sbase + (uint32_t)(kt % NSTG) * STG_B;
        // A: 128 rows x 8 chunks of 16B = 1024 chunks; 2 per thread
#pragma unroll
        for (int i = 0; i < 2; ++i) {
            const int idx = tid + i * 512;
            const int r = idx >> 3, c = idx & 7;
            const void* src = Abase + (size_t)r * KK + kt * BK + c * 8;
            const uint32_t dst = sb + (uint32_t)r * ROWB + (uint32_t)c * 16u;
            asm volatile("cp.async.cg.shared.global [%0], [%1], 16;"
                         :: "r"(dst), "l"(src));
        }
        // B: 128 rows x 8 chunks; 2 per thread
#pragma unroll
        for (int i = 0; i < 2; ++i) {
            const int idx = tid + i * 512;
            const int r = idx >> 3, c = idx & 7;
            const void* src = Bbase + (size_t)r * KK + kt * BK + c * 8;
            const uint32_t dst = sb + (uint32_t)BM * ROWB
                               + (uint32_t)r * ROWB + (uint32_t)c * 16u;
            asm volatile("cp.async.cg.shared.global [%0], [%1], 16;"
                         :: "r"(dst), "l"(src));
        }
        asm volatile("cp.async.commit_group;" ::: "memory");
    };

    float acc[2][4][4] = {};

    issue(0); issue(1);

    const int lrow = lane & 15;
    const int lcb  = (lane >> 4) * 8;

#pragma unroll 1
    for (int kt = 0; kt < KT; ++kt) {
        if (kt + 1 < KT) asm volatile("cp.async.wait_group 1;" ::: "memory");
        else             asm volatile("cp.async.wait_group 0;" ::: "memory");
        __syncthreads();
        if (kt + 2 < KT) issue(kt + 2);

        const uint32_t sb = sbase + (uint32_t)(kt % NSTG) * STG_B;
#pragma unroll
        for (int ks = 0; ks < 4; ++ks) {
            uint32_t a[2][4];
            uint32_t bq[2][4];
#pragma unroll
            for (int mt = 0; mt < 2; ++mt) {
                const uint32_t addr = sb + (uint32_t)(wm + mt * 16 + lrow) * ROWB
                                    + (uint32_t)(ks * 16 + lcb) * 2u;
                asm volatile("ldmatrix.sync.aligned.m8n8.x4.shared.b16 {%0,%1,%2,%3}, [%4];"
                             : "=r"(a[mt][0]), "=r"(a[mt][1]), "=r"(a[mt][2]), "=r"(a[mt][3])
                             : "r"(addr));
            }
#pragma unroll
            for (int np = 0; np < 2; ++np) {
                const uint32_t addr = sb + (uint32_t)BM * ROWB
                                    + (uint32_t)(wn + np * 16 + lrow) * ROWB
                                    + (uint32_t)(ks * 16 + lcb) * 2u;
                asm volatile("ldmatrix.sync.aligned.m8n8.x4.shared.b16 {%0,%1,%2,%3}, [%4];"
                             : "=r"(bq[np][0]), "=r"(bq[np][1]), "=r"(bq[np][2]), "=r"(bq[np][3])
                             : "r"(addr));
            }
#pragma unroll
            for (int mt = 0; mt < 2; ++mt) {
#pragma unroll
                for (int nt = 0; nt < 4; ++nt) {
                    const int np = nt >> 1, pp = nt & 1;
                    asm volatile(
                        "mma.sync.aligned.m16n8k16.row.col.f32.f16.f16.f32 "
                        "{%0,%1,%2,%3}, {%4,%5,%6,%7}, {%8,%9}, {%0,%1,%2,%3};"
                        : "+f"(acc[mt][nt][0]), "+f"(acc[mt][nt][1]),
                          "+f"(acc[mt][nt][2]), "+f"(acc[mt][nt][3])
                        : "r"(a[mt][0]), "r"(a[mt][1]), "r"(a[mt][2]), "r"(a[mt][3]),
                          "r"(bq[np][pp]), "r"(bq[np][pp + 2]));
                }
            }
        }
    }

    // ---- epilogue ----
    const int gr = lane >> 2;
    const int gc = (lane & 3) * 2;
#pragma unroll
    for (int mt = 0; mt < 2; ++mt) {
#pragma unroll
        for (int nt = 0; nt < 4; ++nt) {
            const int row = mb * BM + wm + mt * 16 + gr;
            const int col = nb * BN + wn + nt * 8 + gc;
            float* cp = C + (size_t)row * NV;
            if (NV % BN == 0) {
                cp[col]     = acc[mt][nt][0];
                cp[col + 1] = acc[mt][nt][1];
                cp += (size_t)8 * NV;
                cp[col]     = acc[mt][nt][2];
                cp[col + 1] = acc[mt][nt][3];
            } else {
                if (col < NV)     cp[col]     = acc[mt][nt][0];
                if (col + 1 < NV) cp[col + 1] = acc[mt][nt][1];
                cp += (size_t)8 * NV;
                if (col < NV)     cp[col]     = acc[mt][nt][2];
                if (col + 1 < NV) cp[col + 1] = acc[mt][nt][3];
            }
        }
    }
}

// ---------------------------------------------------------------------------
// Launch
// ---------------------------------------------------------------------------
#define GEMM_SMEM (NSTG * (int)STG_B)   // 110592 B

extern "C" void kernel_launch(void* const* d_in, const int* in_sizes, int n_in,
                              void* d_out, int out_size) {
    (void)in_sizes; (void)n_in; (void)out_size;
    const float* x   = (const float*)d_in[0];
    const float* bw1 = (const float*)d_in[1];
    const float* sw1 = (const float*)d_in[2];
    const float* sc1 = (const float*)d_in[3];
    const float* ga  = (const float*)d_in[4];
    const float* be  = (const float*)d_in[5];
    const float* bw2 = (const float*)d_in[6];
    const float* sw2 = (const float*)d_in[7];
    const float* sc2 = (const float*)d_in[8];
    float* out = (float*)d_out;

    cudaFuncSetAttribute(gemm_hmma<1>,
                         cudaFuncAttributeMaxDynamicSharedMemorySize, GEMM_SMEM);
    cudaFuncSetAttribute(gemm_hmma<2>,
                         cudaFuncAttributeMaxDynamicSharedMemorySize, GEMM_SMEM);

    fusew1_kernel<<<(D_HID * D_IN + 255) / 256, 256>>>(bw1, sw1, sc1);
    fusew2_kernel<<<(N2PAD * D_HID + 255) / 256, 256>>>(bw2, sw2, sc2);
    expand1_kernel<<<(B_SZ * D_IN + 255) / 256, 256>>>(x);

    // GEMM1: N blocks = 512/128 = 4, M blocks = 16384/128 = 128 -> 512 CTAs
    gemm_hmma<1><<<dim3(4, 128), 512, GEMM_SMEM>>>(nullptr);

    ln_expand2_kernel<<<B_SZ, 256>>>(ga, be);

    // GEMM2: N blocks = 256/128 = 2, M blocks = 128 -> 256 CTAs
    gemm_hmma<2><<<dim3(2, 128), 512, GEMM_SMEM>>>(out);
}